// round 1
// baseline (speedup 1.0000x reference)
#include <cuda_runtime.h>
#include <math.h>

#define NB   65536
#define DD   44
#define HH   256
#define EE   4
#define AA   8
#define TILE 32
#define NT   256

// dynamic smem layout (floats):
//   Xs   [TILE][DD]      1408
//   Buf1 [TILE][HH]      8192
//   Buf2 [TILE][HH]      8192
//   lg   [TILE][EE]       128
//   comb [TILE][EE]       128
#define SMEM_FLOATS (TILE*DD + 2*TILE*HH + 2*TILE*EE)
#define SMEM_BYTES  (SMEM_FLOATS * 4)

__device__ __forceinline__ float softplus1(float x) {
    // softplus(x) + 1, overflow-safe
    return fmaxf(x, 0.f) + log1pf(expf(-fabsf(x))) + 1.f;
}

// Row-wise LayerNorm (width 256) + affine + ReLU, in place on Buf[TILE][256].
// 8 warps x 4 rows. Callers sync before & after.
__device__ __forceinline__ void ln_relu_256(float* Buf, const float* __restrict__ g,
                                            const float* __restrict__ b, int t) {
    const int warp = t >> 5, lane = t & 31;
    #pragma unroll
    for (int rr = 0; rr < 4; rr++) {
        const int r = warp * 4 + rr;
        float s = 0.f, ss = 0.f;
        #pragma unroll
        for (int i = 0; i < 8; i++) {
            float v = Buf[r * HH + lane + i * 32];
            s += v; ss += v * v;
        }
        #pragma unroll
        for (int o = 16; o > 0; o >>= 1) {
            s  += __shfl_xor_sync(0xffffffffu, s,  o);
            ss += __shfl_xor_sync(0xffffffffu, ss, o);
        }
        const float mean = s * (1.f / 256.f);
        const float var  = ss * (1.f / 256.f) - mean * mean;
        const float rstd = rsqrtf(var + 1e-5f);
        #pragma unroll
        for (int i = 0; i < 8; i++) {
            const int c = lane + i * 32;
            float v = Buf[r * HH + c];
            Buf[r * HH + c] = fmaxf((v - mean) * rstd * g[c] + b[c], 0.f);
        }
    }
}

// Y[TILE][256] = Xs[TILE][44] @ W[44][256] + bias  (raw, no activation)
__device__ __forceinline__ void gemm_d44(const float* Xs, const float* __restrict__ W,
                                         const float* __restrict__ bias, float* Out, int t) {
    float acc[TILE];
    #pragma unroll
    for (int r = 0; r < TILE; r++) acc[r] = 0.f;
    const int c = t;  // 256 threads = 256 columns
    for (int k = 0; k < DD; k += 4) {
        const float w0 = W[(k + 0) * HH + c];
        const float w1 = W[(k + 1) * HH + c];
        const float w2 = W[(k + 2) * HH + c];
        const float w3 = W[(k + 3) * HH + c];
        #pragma unroll
        for (int r = 0; r < TILE; r++) {
            const float4 x = *(const float4*)&Xs[r * DD + k];
            acc[r] = fmaf(x.x, w0, acc[r]);
            acc[r] = fmaf(x.y, w1, acc[r]);
            acc[r] = fmaf(x.z, w2, acc[r]);
            acc[r] = fmaf(x.w, w3, acc[r]);
        }
    }
    const float bb = bias[c];
    #pragma unroll
    for (int r = 0; r < TILE; r++) Out[r * HH + c] = acc[r] + bb;
}

// Y[TILE][256] = In[TILE][256] @ W[256][256] + bias  (raw)
__device__ __forceinline__ void gemm_h256(const float* In, const float* __restrict__ W,
                                          const float* __restrict__ bias, float* Out, int t) {
    float acc[TILE];
    #pragma unroll
    for (int r = 0; r < TILE; r++) acc[r] = 0.f;
    const int c = t;
    for (int k = 0; k < HH; k += 4) {
        const float w0 = W[(k + 0) * HH + c];
        const float w1 = W[(k + 1) * HH + c];
        const float w2 = W[(k + 2) * HH + c];
        const float w3 = W[(k + 3) * HH + c];
        #pragma unroll
        for (int r = 0; r < TILE; r++) {
            const float4 x = *(const float4*)&In[r * HH + k];
            acc[r] = fmaf(x.x, w0, acc[r]);
            acc[r] = fmaf(x.y, w1, acc[r]);
            acc[r] = fmaf(x.z, w2, acc[r]);
            acc[r] = fmaf(x.w, w3, acc[r]);
        }
    }
    const float bb = bias[c];
    #pragma unroll
    for (int r = 0; r < TILE; r++) Out[r * HH + c] = acc[r] + bb;
}

__global__ void __launch_bounds__(NT) moe_fused_kernel(
    const float* __restrict__ state,
    const float* __restrict__ rW1, const float* __restrict__ rb1,
    const float* __restrict__ rW2, const float* __restrict__ rb2,
    const float* __restrict__ eW1, const float* __restrict__ eb1,
    const float* __restrict__ eg1, const float* __restrict__ ebt1,
    const float* __restrict__ eW2, const float* __restrict__ eb2,
    const float* __restrict__ eg2, const float* __restrict__ ebt2,
    const float* __restrict__ eW3, const float* __restrict__ eb3,
    const float* __restrict__ vW1, const float* __restrict__ vb1,
    const float* __restrict__ vg,  const float* __restrict__ vbt,
    const float* __restrict__ vW2, const float* __restrict__ vb2,
    const float* __restrict__ vW3, const float* __restrict__ vb3,
    float* __restrict__ out)
{
    extern __shared__ float sm[];
    float* Xs   = sm;                    // TILE*DD
    float* Buf1 = Xs + TILE * DD;        // TILE*HH
    float* Buf2 = Buf1 + TILE * HH;      // TILE*HH
    float* lg   = Buf2 + TILE * HH;      // TILE*EE
    float* comb = lg + TILE * EE;        // TILE*EE

    const int t = threadIdx.x;
    const int row0 = blockIdx.x * TILE;

    // ---- load state tile ----
    for (int i = t; i < TILE * DD; i += NT) {
        const int r = i / DD, c = i - r * DD;
        Xs[i] = state[(size_t)(row0 + r) * DD + c];
    }
    __syncthreads();

    // ---- router hidden: h = relu(X @ rW1 + rb1) -> Buf2[TILE][128] ----
    {
        const int c = t & 127;
        const int rbase = (t >> 7) * 16;
        float acc[16];
        #pragma unroll
        for (int r = 0; r < 16; r++) acc[r] = 0.f;
        for (int k = 0; k < DD; k += 4) {
            const float w0 = rW1[(k + 0) * 128 + c];
            const float w1 = rW1[(k + 1) * 128 + c];
            const float w2 = rW1[(k + 2) * 128 + c];
            const float w3 = rW1[(k + 3) * 128 + c];
            #pragma unroll
            for (int r = 0; r < 16; r++) {
                const float4 x = *(const float4*)&Xs[(rbase + r) * DD + k];
                acc[r] = fmaf(x.x, w0, acc[r]);
                acc[r] = fmaf(x.y, w1, acc[r]);
                acc[r] = fmaf(x.z, w2, acc[r]);
                acc[r] = fmaf(x.w, w3, acc[r]);
            }
        }
        const float bb = rb1[c];
        #pragma unroll
        for (int r = 0; r < 16; r++)
            Buf2[(rbase + r) * 128 + c] = fmaxf(acc[r] + bb, 0.f);
    }
    __syncthreads();

    // ---- router logits [TILE][4] ----
    if (t < TILE * EE) {
        const int r = t >> 2, e = t & 3;
        float acc = rb2[e];
        for (int k = 0; k < 128; k++)
            acc = fmaf(Buf2[r * 128 + k], rW2[k * EE + e], acc);
        lg[r * EE + e] = acc;
    }
    __syncthreads();

    // ---- softmax, top-2, combine weights, write router_probs ----
    if (t < TILE) {
        float l[4];
        #pragma unroll
        for (int e = 0; e < 4; e++) l[e] = lg[t * 4 + e];
        float m = fmaxf(fmaxf(l[0], l[1]), fmaxf(l[2], l[3]));
        float p[4], s = 0.f;
        #pragma unroll
        for (int e = 0; e < 4; e++) { p[e] = expf(l[e] - m); s += p[e]; }
        const float inv = 1.f / s;
        #pragma unroll
        for (int e = 0; e < 4; e++) p[e] *= inv;

        const size_t rbase = (size_t)NB * 17 + (size_t)(row0 + t) * 4;
        #pragma unroll
        for (int e = 0; e < 4; e++) out[rbase + e] = p[e];

        int i0 = 0; float v0 = p[0];
        #pragma unroll
        for (int e = 1; e < 4; e++) if (p[e] > v0) { v0 = p[e]; i0 = e; }
        int i1 = -1; float v1 = -1.f;
        #pragma unroll
        for (int e = 0; e < 4; e++) if (e != i0 && p[e] > v1) { v1 = p[e]; i1 = e; }
        const float denom = 1.f / (v0 + v1 + 1e-8f);
        #pragma unroll
        for (int e = 0; e < 4; e++) comb[t * 4 + e] = 0.f;
        comb[t * 4 + i0] = v0 * denom;
        comb[t * 4 + i1] = v1 * denom;
    }
    __syncthreads();

    // ---- value net: v1 = relu(ln(X @ vW1 + vb1)) -> Buf1 ----
    gemm_d44(Xs, vW1, vb1, Buf1, t);
    __syncthreads();
    ln_relu_256(Buf1, vg, vbt, t);
    __syncthreads();

    // v2 = relu(v1 @ vW2 + vb2) -> Buf2[TILE][128]
    {
        const int c = t & 127;
        const int rbase = (t >> 7) * 16;
        float acc[16];
        #pragma unroll
        for (int r = 0; r < 16; r++) acc[r] = 0.f;
        for (int k = 0; k < HH; k += 4) {
            const float w0 = vW2[(k + 0) * 128 + c];
            const float w1 = vW2[(k + 1) * 128 + c];
            const float w2 = vW2[(k + 2) * 128 + c];
            const float w3 = vW2[(k + 3) * 128 + c];
            #pragma unroll
            for (int r = 0; r < 16; r++) {
                const float4 x = *(const float4*)&Buf1[(rbase + r) * HH + k];
                acc[r] = fmaf(x.x, w0, acc[r]);
                acc[r] = fmaf(x.y, w1, acc[r]);
                acc[r] = fmaf(x.z, w2, acc[r]);
                acc[r] = fmaf(x.w, w3, acc[r]);
            }
        }
        const float bb = vb2[c];
        #pragma unroll
        for (int r = 0; r < 16; r++)
            Buf2[(rbase + r) * 128 + c] = fmaxf(acc[r] + bb, 0.f);
    }
    __syncthreads();

    // value = v2 @ vW3 + vb3  (8 warps x 4 rows)
    {
        const int warp = t >> 5, lane = t & 31;
        #pragma unroll
        for (int rr = 0; rr < 4; rr++) {
            const int r = warp * 4 + rr;
            float acc = 0.f;
            #pragma unroll
            for (int i = 0; i < 4; i++) {
                const int k = lane + i * 32;
                acc = fmaf(Buf2[r * 128 + k], vW3[k], acc);
            }
            #pragma unroll
            for (int o = 16; o > 0; o >>= 1)
                acc += __shfl_xor_sync(0xffffffffu, acc, o);
            if (lane == 0)
                out[(size_t)NB * 16 + (row0 + r)] = acc + vb3[0];
        }
    }
    __syncthreads();

    // ---- experts (dense over all 4, weighted by combine) ----
    const int col = t & 15;          // output column in [0,16)
    const int rA  = t >> 4;          // rows rA and rA+16
    float mixA = 0.f, mixB = 0.f;

    for (int e = 0; e < EE; e++) {
        const float* W1 = eW1 + (size_t)e * DD * HH;
        const float* W2 = eW2 + (size_t)e * HH * HH;
        const float* W3 = eW3 + (size_t)e * HH * 16;

        gemm_d44(Xs, W1, eb1 + e * HH, Buf1, t);
        __syncthreads();
        ln_relu_256(Buf1, eg1 + e * HH, ebt1 + e * HH, t);
        __syncthreads();

        gemm_h256(Buf1, W2, eb2 + e * HH, Buf2, t);
        __syncthreads();
        ln_relu_256(Buf2, eg2 + e * HH, ebt2 + e * HH, t);
        __syncthreads();

        // out3[TILE][16] = Buf2 @ W3 + b3; accumulate into mix registers
        float a0 = 0.f, a1 = 0.f;
        for (int k = 0; k < HH; k += 4) {
            const float w0 = W3[(k + 0) * 16 + col];
            const float w1 = W3[(k + 1) * 16 + col];
            const float w2 = W3[(k + 2) * 16 + col];
            const float w3 = W3[(k + 3) * 16 + col];
            const float4 xA = *(const float4*)&Buf2[rA * HH + k];
            const float4 xB = *(const float4*)&Buf2[(rA + 16) * HH + k];
            a0 = fmaf(xA.x, w0, a0); a0 = fmaf(xA.y, w1, a0);
            a0 = fmaf(xA.z, w2, a0); a0 = fmaf(xA.w, w3, a0);
            a1 = fmaf(xB.x, w0, a1); a1 = fmaf(xB.y, w1, a1);
            a1 = fmaf(xB.z, w2, a1); a1 = fmaf(xB.w, w3, a1);
        }
        const float b3v = eb3[e * 16 + col];
        mixA = fmaf(comb[rA * 4 + e],        a0 + b3v, mixA);
        mixB = fmaf(comb[(rA + 16) * 4 + e], a1 + b3v, mixB);
        __syncthreads();
    }

    // ---- epilogue: alpha / beta ----
    {
        const float oA = softplus1(mixA);
        const float oB = softplus1(mixB);
        const size_t rowAg = row0 + rA;
        const size_t rowBg = rowAg + 16;
        if (col < AA) {
            out[rowAg * AA + col] = oA;
            out[rowBg * AA + col] = oB;
        } else {
            out[(size_t)NB * AA + rowAg * AA + (col - AA)] = oA;
            out[(size_t)NB * AA + rowBg * AA + (col - AA)] = oB;
        }
    }
}

extern "C" void kernel_launch(void* const* d_in, const int* in_sizes, int n_in,
                              void* d_out, int out_size) {
    const float* state = (const float*)d_in[0];
    const float* rW1   = (const float*)d_in[1];
    const float* rb1   = (const float*)d_in[2];
    const float* rW2   = (const float*)d_in[3];
    const float* rb2   = (const float*)d_in[4];
    const float* eW1   = (const float*)d_in[5];
    const float* eb1   = (const float*)d_in[6];
    const float* eg1   = (const float*)d_in[7];
    const float* ebt1  = (const float*)d_in[8];
    const float* eW2   = (const float*)d_in[9];
    const float* eb2   = (const float*)d_in[10];
    const float* eg2   = (const float*)d_in[11];
    const float* ebt2  = (const float*)d_in[12];
    const float* eW3   = (const float*)d_in[13];
    const float* eb3   = (const float*)d_in[14];
    const float* vW1   = (const float*)d_in[15];
    const float* vb1   = (const float*)d_in[16];
    const float* vg    = (const float*)d_in[17];
    const float* vbt   = (const float*)d_in[18];
    const float* vW2   = (const float*)d_in[19];
    const float* vb2   = (const float*)d_in[20];
    const float* vW3   = (const float*)d_in[21];
    const float* vb3   = (const float*)d_in[22];
    float* out = (float*)d_out;

    cudaFuncSetAttribute(moe_fused_kernel,
                         cudaFuncAttributeMaxDynamicSharedMemorySize, SMEM_BYTES);

    moe_fused_kernel<<<NB / TILE, NT, SMEM_BYTES>>>(
        state, rW1, rb1, rW2, rb2,
        eW1, eb1, eg1, ebt1, eW2, eb2, eg2, ebt2, eW3, eb3,
        vW1, vb1, vg, vbt, vW2, vb2, vW3, vb3, out);
}

// round 2
// speedup vs baseline: 1.1390x; 1.1390x over previous
#include <cuda_runtime.h>
#include <math.h>

typedef unsigned long long u64;

#define NB   65536
#define DD   44
#define HH   256
#define EE   4
#define AA   8
#define TILE 32
#define NT   256

// dynamic smem layout (floats) — all activation buffers TRANSPOSED: buf[feature][row]
#define OFF_A1   (TILE*DD)                 // XsT: [0,1408)
#define OFF_A2   (OFF_A1 + HH*TILE)        // A1:  [1408,9600)
#define OFF_RED  (OFF_A2 + HH*TILE)        // A2:  [9600,17792)
#define OFF_MROW (OFF_RED + 512)           // red: [17792,18304)
#define OFF_RROW (OFF_MROW + 32)
#define OFF_LG   (OFF_RROW + 32)           // lg:  [18368,18496)
#define OFF_COMB (OFF_LG + TILE*EE)        // combT [e][32]: [18496,18624)
#define SMEM_FLOATS (OFF_COMB + EE*TILE)
#define SMEM_BYTES  (SMEM_FLOATS * 4)

// ---------- packed f32x2 helpers ----------
__device__ __forceinline__ u64 ffma2(u64 a, u64 b, u64 c) {
    u64 d;
    asm("fma.rn.f32x2 %0, %1, %2, %3;" : "=l"(d) : "l"(a), "l"(b), "l"(c));
    return d;
}
__device__ __forceinline__ u64 fadd2(u64 a, u64 b) {
    u64 d;
    asm("add.rn.f32x2 %0, %1, %2;" : "=l"(d) : "l"(a), "l"(b));
    return d;
}
__device__ __forceinline__ u64 dup2(float w) {
    u64 d; unsigned int ui = __float_as_uint(w);
    asm("mov.b64 %0, {%1, %1};" : "=l"(d) : "r"(ui));
    return d;
}
__device__ __forceinline__ float2 unpack2(u64 a) {
    float2 f;
    asm("mov.b64 {%0, %1}, %2;" : "=f"(f.x), "=f"(f.y) : "l"(a));
    return f;
}
__device__ __forceinline__ float softplus1(float x) {
    return fmaxf(x, 0.f) + log1pf(expf(-fabsf(x))) + 1.f;
}

// ---------- GEMM: In^T[K][32] @ W[K][256] -> Out^T[256][32] (+bias, raw) ----------
// thread tile: 8 rows (4 packed pairs) x 4 cols
template<int K>
__device__ __forceinline__ void gemm_to256(const float* In, const float* __restrict__ W,
                                           const float* __restrict__ bias, float* Out, int t)
{
    const int c0 = (t & 63) * 4;
    const int r0 = (t >> 6) * 8;
    u64 acc[4][4];
    #pragma unroll
    for (int p = 0; p < 4; p++)
        #pragma unroll
        for (int j = 0; j < 4; j++) acc[p][j] = 0ull;

    #pragma unroll 2
    for (int k = 0; k < K; k++) {
        const double2 xa = *(const double2*)(In + k * TILE + r0);
        const double2 xb = *(const double2*)(In + k * TILE + r0 + 4);
        u64 xs[4];
        xs[0] = __double_as_longlong(xa.x); xs[1] = __double_as_longlong(xa.y);
        xs[2] = __double_as_longlong(xb.x); xs[3] = __double_as_longlong(xb.y);
        const float4 wv = *(const float4*)(W + k * HH + c0);
        u64 w2[4] = { dup2(wv.x), dup2(wv.y), dup2(wv.z), dup2(wv.w) };
        #pragma unroll
        for (int p = 0; p < 4; p++)
            #pragma unroll
            for (int j = 0; j < 4; j++)
                acc[p][j] = ffma2(xs[p], w2[j], acc[p][j]);
    }

    #pragma unroll
    for (int j = 0; j < 4; j++) {
        const u64 b2 = dup2(bias[c0 + j]);
        const float2 f0 = unpack2(fadd2(acc[0][j], b2));
        const float2 f1 = unpack2(fadd2(acc[1][j], b2));
        const float2 f2 = unpack2(fadd2(acc[2][j], b2));
        const float2 f3 = unpack2(fadd2(acc[3][j], b2));
        *(float4*)(Out + (c0 + j) * TILE + r0)     = make_float4(f0.x, f0.y, f1.x, f1.y);
        *(float4*)(Out + (c0 + j) * TILE + r0 + 4) = make_float4(f2.x, f2.y, f3.x, f3.y);
    }
}

// ---------- GEMM: In^T[K][32] @ W[K][128] -> Out^T[128][32], +bias, ReLU ----------
// thread tile: 16 rows (8 pairs) x 1 col
template<int K>
__device__ __forceinline__ void gemm_to128_relu(const float* In, const float* __restrict__ W,
                                                const float* __restrict__ bias, float* Out, int t)
{
    const int c  = t & 127;
    const int r0 = (t >> 7) * 16;
    u64 acc[8];
    #pragma unroll
    for (int p = 0; p < 8; p++) acc[p] = 0ull;

    #pragma unroll 2
    for (int k = 0; k < K; k++) {
        const double2 x0 = *(const double2*)(In + k * TILE + r0);
        const double2 x1 = *(const double2*)(In + k * TILE + r0 + 4);
        const double2 x2 = *(const double2*)(In + k * TILE + r0 + 8);
        const double2 x3 = *(const double2*)(In + k * TILE + r0 + 12);
        const u64 w2 = dup2(W[k * 128 + c]);
        acc[0] = ffma2(__double_as_longlong(x0.x), w2, acc[0]);
        acc[1] = ffma2(__double_as_longlong(x0.y), w2, acc[1]);
        acc[2] = ffma2(__double_as_longlong(x1.x), w2, acc[2]);
        acc[3] = ffma2(__double_as_longlong(x1.y), w2, acc[3]);
        acc[4] = ffma2(__double_as_longlong(x2.x), w2, acc[4]);
        acc[5] = ffma2(__double_as_longlong(x2.y), w2, acc[5]);
        acc[6] = ffma2(__double_as_longlong(x3.x), w2, acc[6]);
        acc[7] = ffma2(__double_as_longlong(x3.y), w2, acc[7]);
    }

    const float bb = bias[c];
    float o[16];
    #pragma unroll
    for (int p = 0; p < 8; p++) {
        const float2 f = unpack2(acc[p]);
        o[2 * p]     = fmaxf(f.x + bb, 0.f);
        o[2 * p + 1] = fmaxf(f.y + bb, 0.f);
    }
    #pragma unroll
    for (int q = 0; q < 4; q++)
        *(float4*)(Out + c * TILE + r0 + 4 * q) =
            make_float4(o[4 * q], o[4 * q + 1], o[4 * q + 2], o[4 * q + 3]);
}

// ---------- LayerNorm(+affine,+ReLU) over feature dim on transposed buf A[256][32] ----------
__device__ __forceinline__ void ln_relu_T(float* A, const float* __restrict__ g,
                                          const float* __restrict__ b,
                                          float* red, float* mrow, float* rrow, int t)
{
    const int r = t & 31, kg = t >> 5;
    float s = 0.f, ss = 0.f;
    #pragma unroll 8
    for (int i = 0; i < 32; i++) {
        const float v = A[(kg * 32 + i) * TILE + r];
        s += v; ss += v * v;
    }
    red[kg * 32 + r] = s;
    red[256 + kg * 32 + r] = ss;
    __syncthreads();
    if (t < 32) {
        float S = 0.f, SS = 0.f;
        #pragma unroll
        for (int j = 0; j < 8; j++) { S += red[j * 32 + t]; SS += red[256 + j * 32 + t]; }
        const float m = S * (1.f / 256.f);
        const float var = SS * (1.f / 256.f) - m * m;
        mrow[t] = m;
        rrow[t] = rsqrtf(var + 1e-5f);
    }
    __syncthreads();
    const float m = mrow[r], rs = rrow[r];
    #pragma unroll 4
    for (int i = 0; i < 32; i++) {
        const int k = kg * 32 + i;
        const int idx = k * TILE + r;
        A[idx] = fmaxf((A[idx] - m) * rs * g[k] + b[k], 0.f);
    }
    __syncthreads();
}

__global__ void __launch_bounds__(NT, 3) moe_fused_kernel(
    const float* __restrict__ state,
    const float* __restrict__ rW1, const float* __restrict__ rb1,
    const float* __restrict__ rW2, const float* __restrict__ rb2,
    const float* __restrict__ eW1, const float* __restrict__ eb1,
    const float* __restrict__ eg1, const float* __restrict__ ebt1,
    const float* __restrict__ eW2, const float* __restrict__ eb2,
    const float* __restrict__ eg2, const float* __restrict__ ebt2,
    const float* __restrict__ eW3, const float* __restrict__ eb3,
    const float* __restrict__ vW1, const float* __restrict__ vb1,
    const float* __restrict__ vg,  const float* __restrict__ vbt,
    const float* __restrict__ vW2, const float* __restrict__ vb2,
    const float* __restrict__ vW3, const float* __restrict__ vb3,
    float* __restrict__ out)
{
    extern __shared__ float sm[];
    float* XsT   = sm;               // [44][32]
    float* A1    = sm + OFF_A1;      // [256][32]
    float* A2    = sm + OFF_A2;      // [256][32]
    float* red   = sm + OFF_RED;     // [512]
    float* mrow  = sm + OFF_MROW;    // [32]
    float* rrow  = sm + OFF_RROW;    // [32]
    float* lg    = sm + OFF_LG;      // [32][4]
    float* combT = sm + OFF_COMB;    // [4][32]

    const int t = threadIdx.x;
    const int row0 = blockIdx.x * TILE;

    // ---- load state tile transposed: XsT[k][r] ----
    for (int i = t; i < TILE * DD; i += NT) {
        const int r = i / DD, k = i - r * DD;
        XsT[k * TILE + r] = state[(size_t)row0 * DD + i];
    }
    __syncthreads();

    // ---- router hidden: relu(X @ rW1 + rb1) -> A2^T[128][32] ----
    gemm_to128_relu<DD>(XsT, rW1, rb1, A2, t);
    __syncthreads();

    // ---- router logits partials ----
    if (t < 128) {
        const int r = t & 31, kg = t >> 5;
        float a0 = 0.f, a1 = 0.f, a2 = 0.f, a3 = 0.f;
        #pragma unroll 4
        for (int i = 0; i < 32; i++) {
            const int k = kg * 32 + i;
            const float x = A2[k * TILE + r];
            a0 = fmaf(x, rW2[k * 4 + 0], a0);
            a1 = fmaf(x, rW2[k * 4 + 1], a1);
            a2 = fmaf(x, rW2[k * 4 + 2], a2);
            a3 = fmaf(x, rW2[k * 4 + 3], a3);
        }
        red[(0 * 4 + kg) * 32 + r] = a0;
        red[(1 * 4 + kg) * 32 + r] = a1;
        red[(2 * 4 + kg) * 32 + r] = a2;
        red[(3 * 4 + kg) * 32 + r] = a3;
    }
    __syncthreads();
    if (t < 128) {
        const int r = t & 31, e = t >> 5;
        float acc = rb2[e];
        #pragma unroll
        for (int kg = 0; kg < 4; kg++) acc += red[(e * 4 + kg) * 32 + r];
        lg[r * 4 + e] = acc;
    }
    __syncthreads();

    // ---- softmax, top-2, combine weights (transposed), router_probs out ----
    if (t < TILE) {
        float l[4];
        #pragma unroll
        for (int e = 0; e < 4; e++) l[e] = lg[t * 4 + e];
        const float m = fmaxf(fmaxf(l[0], l[1]), fmaxf(l[2], l[3]));
        float p[4], s = 0.f;
        #pragma unroll
        for (int e = 0; e < 4; e++) { p[e] = expf(l[e] - m); s += p[e]; }
        const float inv = 1.f / s;
        #pragma unroll
        for (int e = 0; e < 4; e++) p[e] *= inv;

        const size_t rbase = (size_t)NB * 17 + (size_t)(row0 + t) * 4;
        #pragma unroll
        for (int e = 0; e < 4; e++) out[rbase + e] = p[e];

        int i0 = 0; float v0 = p[0];
        #pragma unroll
        for (int e = 1; e < 4; e++) if (p[e] > v0) { v0 = p[e]; i0 = e; }
        int i1 = -1; float v1 = -1.f;
        #pragma unroll
        for (int e = 0; e < 4; e++) if (e != i0 && p[e] > v1) { v1 = p[e]; i1 = e; }
        const float denom = 1.f / (v0 + v1 + 1e-8f);
        #pragma unroll
        for (int e = 0; e < 4; e++) combT[e * 32 + t] = 0.f;
        combT[i0 * 32 + t] = v0 * denom;
        combT[i1 * 32 + t] = v1 * denom;
    }

    // ---- value net ----
    gemm_to256<DD>(XsT, vW1, vb1, A1, t);
    __syncthreads();
    ln_relu_T(A1, vg, vbt, red, mrow, rrow, t);       // includes trailing sync
    gemm_to128_relu<HH>(A1, vW2, vb2, A2, t);
    __syncthreads();
    {   // value = v2 @ vW3 + vb3
        const int r = t & 31, kg = t >> 5;
        float s = 0.f;
        #pragma unroll 4
        for (int i = 0; i < 16; i++) {
            const int k = kg * 16 + i;
            s = fmaf(A2[k * TILE + r], vW3[k], s);
        }
        red[kg * 32 + r] = s;
    }
    __syncthreads();
    if (t < 32) {
        float S = 0.f;
        #pragma unroll
        for (int j = 0; j < 8; j++) S += red[j * 32 + t];
        out[(size_t)NB * 16 + row0 + t] = S + vb3[0];
    }

    // ---- experts: dense over 4, weighted accumulate in packed registers ----
    const int ec = t & 15;    // output column 0..15
    const int ep = t >> 4;    // row pair 0..15 -> rows 2ep, 2ep+1
    u64 mix2 = 0ull;

    for (int e = 0; e < EE; e++) {
        const float* W1 = eW1 + (size_t)e * DD * HH;
        const float* W2 = eW2 + (size_t)e * HH * HH;
        const float* W3 = eW3 + (size_t)e * HH * 16;

        gemm_to256<DD>(XsT, W1, eb1 + e * HH, A1, t);
        __syncthreads();
        ln_relu_T(A1, eg1 + e * HH, ebt1 + e * HH, red, mrow, rrow, t);

        gemm_to256<HH>(A1, W2, eb2 + e * HH, A2, t);
        __syncthreads();
        ln_relu_T(A2, eg2 + e * HH, ebt2 + e * HH, red, mrow, rrow, t);

        // GEMM3: A2^T[256][32] @ W3[256][16], weighted by combine
        u64 a2 = 0ull;
        #pragma unroll 4
        for (int k = 0; k < HH; k++) {
            const u64 x  = __double_as_longlong(*(const double*)(A2 + k * TILE + 2 * ep));
            const u64 w2 = dup2(W3[k * 16 + ec]);
            a2 = ffma2(x, w2, a2);
        }
        const u64 b2 = dup2(eb3[e * 16 + ec]);
        const u64 y  = fadd2(a2, b2);
        const u64 cw = __double_as_longlong(*(const double*)(combT + e * 32 + 2 * ep));
        mix2 = ffma2(cw, y, mix2);
        // no extra sync: next gemm writes A1 only; A2 rewrite is gated by later syncs
    }

    // ---- epilogue: alpha / beta ----
    {
        const float2 mm = unpack2(mix2);
        const float oA = softplus1(mm.x);
        const float oB = softplus1(mm.y);
        const size_t rowA = row0 + 2 * ep;
        const size_t rowB = rowA + 1;
        if (ec < AA) {
            out[rowA * AA + ec] = oA;
            out[rowB * AA + ec] = oB;
        } else {
            out[(size_t)NB * AA + rowA * AA + (ec - AA)] = oA;
            out[(size_t)NB * AA + rowB * AA + (ec - AA)] = oB;
        }
    }
}

extern "C" void kernel_launch(void* const* d_in, const int* in_sizes, int n_in,
                              void* d_out, int out_size) {
    const float* state = (const float*)d_in[0];
    const float* rW1   = (const float*)d_in[1];
    const float* rb1   = (const float*)d_in[2];
    const float* rW2   = (const float*)d_in[3];
    const float* rb2   = (const float*)d_in[4];
    const float* eW1   = (const float*)d_in[5];
    const float* eb1   = (const float*)d_in[6];
    const float* eg1   = (const float*)d_in[7];
    const float* ebt1  = (const float*)d_in[8];
    const float* eW2   = (const float*)d_in[9];
    const float* eb2   = (const float*)d_in[10];
    const float* eg2   = (const float*)d_in[11];
    const float* ebt2  = (const float*)d_in[12];
    const float* eW3   = (const float*)d_in[13];
    const float* eb3   = (const float*)d_in[14];
    const float* vW1   = (const float*)d_in[15];
    const float* vb1   = (const float*)d_in[16];
    const float* vg    = (const float*)d_in[17];
    const float* vbt   = (const float*)d_in[18];
    const float* vW2   = (const float*)d_in[19];
    const float* vb2   = (const float*)d_in[20];
    const float* vW3   = (const float*)d_in[21];
    const float* vb3   = (const float*)d_in[22];
    float* out = (float*)d_out;

    cudaFuncSetAttribute(moe_fused_kernel,
                         cudaFuncAttributeMaxDynamicSharedMemorySize, SMEM_BYTES);

    moe_fused_kernel<<<NB / TILE, NT, SMEM_BYTES>>>(
        state, rW1, rb1, rW2, rb2,
        eW1, eb1, eg1, ebt1, eW2, eb2, eg2, ebt2, eW3, eb3,
        vW1, vb1, vg, vbt, vW2, vb2, vW3, vb3, out);
}

// round 3
// speedup vs baseline: 1.3104x; 1.1505x over previous
#include <cuda_runtime.h>
#include <math.h>

typedef unsigned long long u64;

#define NB   65536
#define DD   44
#define HH   256
#define EE   4
#define AA   8
#define TILE 32
#define NT   256

// dynamic smem layout (floats) — all activation buffers TRANSPOSED: buf[feature][row]
#define OFF_A1   (TILE*DD)
#define OFF_A2   (OFF_A1 + HH*TILE)
#define OFF_RED  (OFF_A2 + HH*TILE)
#define OFF_MROW (OFF_RED + 512)
#define OFF_RROW (OFF_MROW + 32)
#define OFF_LG   (OFF_RROW + 32)
#define OFF_COMB (OFF_LG + TILE*EE)
#define SMEM_FLOATS (OFF_COMB + EE*TILE)
#define SMEM_BYTES  (SMEM_FLOATS * 4)

// ---------- packed f32x2 helpers ----------
__device__ __forceinline__ u64 ffma2(u64 a, u64 b, u64 c) {
    u64 d;
    asm("fma.rn.f32x2 %0, %1, %2, %3;" : "=l"(d) : "l"(a), "l"(b), "l"(c));
    return d;
}
__device__ __forceinline__ u64 fadd2(u64 a, u64 b) {
    u64 d;
    asm("add.rn.f32x2 %0, %1, %2;" : "=l"(d) : "l"(a), "l"(b));
    return d;
}
__device__ __forceinline__ u64 dup2(float w) {
    u64 d; unsigned int ui = __float_as_uint(w);
    asm("mov.b64 %0, {%1, %1};" : "=l"(d) : "r"(ui));
    return d;
}
__device__ __forceinline__ float2 unpack2(u64 a) {
    float2 f;
    asm("mov.b64 {%0, %1}, %2;" : "=f"(f.x), "=f"(f.y) : "l"(a));
    return f;
}
__device__ __forceinline__ float softplus1(float x) {
    return fmaxf(x, 0.f) + log1pf(expf(-fabsf(x))) + 1.f;
}

// ---------- GEMM: In^T[K][32] @ W[K][256] -> Out^T[256][32] (+bias, raw) ----------
// thread tile: 8 rows (4 packed pairs) x 4 cols. K % 4 == 0.
// Weight LDGs batched 4-deep (MLP=4) to hide L2 latency.
template<int K>
__device__ __forceinline__ void gemm_to256(const float* In, const float* __restrict__ W,
                                           const float* __restrict__ bias, float* Out, int t)
{
    const int c0 = (t & 63) * 4;
    const int r0 = (t >> 6) * 8;
    u64 acc[4][4];
    #pragma unroll
    for (int p = 0; p < 4; p++)
        #pragma unroll
        for (int j = 0; j < 4; j++) acc[p][j] = 0ull;

    const float* Wp = W + c0;

    #pragma unroll 2
    for (int k0 = 0; k0 < K; k0 += 4) {
        // batch the 4 weight LDG.128s up front
        float4 wv[4];
        #pragma unroll
        for (int j = 0; j < 4; j++)
            wv[j] = *(const float4*)(Wp + (k0 + j) * HH);

        #pragma unroll
        for (int j = 0; j < 4; j++) {
            const int k = k0 + j;
            const double2 xa = *(const double2*)(In + k * TILE + r0);
            const double2 xb = *(const double2*)(In + k * TILE + r0 + 4);
            u64 xs[4];
            xs[0] = __double_as_longlong(xa.x); xs[1] = __double_as_longlong(xa.y);
            xs[2] = __double_as_longlong(xb.x); xs[3] = __double_as_longlong(xb.y);
            u64 w2[4] = { dup2(wv[j].x), dup2(wv[j].y), dup2(wv[j].z), dup2(wv[j].w) };
            #pragma unroll
            for (int p = 0; p < 4; p++)
                #pragma unroll
                for (int q = 0; q < 4; q++)
                    acc[p][q] = ffma2(xs[p], w2[q], acc[p][q]);
        }
    }

    #pragma unroll
    for (int j = 0; j < 4; j++) {
        const u64 b2 = dup2(bias[c0 + j]);
        const float2 f0 = unpack2(fadd2(acc[0][j], b2));
        const float2 f1 = unpack2(fadd2(acc[1][j], b2));
        const float2 f2 = unpack2(fadd2(acc[2][j], b2));
        const float2 f3 = unpack2(fadd2(acc[3][j], b2));
        *(float4*)(Out + (c0 + j) * TILE + r0)     = make_float4(f0.x, f0.y, f1.x, f1.y);
        *(float4*)(Out + (c0 + j) * TILE + r0 + 4) = make_float4(f2.x, f2.y, f3.x, f3.y);
    }
}

// ---------- GEMM: In^T[K][32] @ W[K][128] -> Out^T[128][32], +bias, ReLU ----------
// thread tile: 16 rows (8 pairs) x 1 col. K % 4 == 0. Weight LDGs batched 4-deep.
template<int K>
__device__ __forceinline__ void gemm_to128_relu(const float* In, const float* __restrict__ W,
                                                const float* __restrict__ bias, float* Out, int t)
{
    const int c  = t & 127;
    const int r0 = (t >> 7) * 16;
    u64 acc[8];
    #pragma unroll
    for (int p = 0; p < 8; p++) acc[p] = 0ull;

    const float* Wp = W + c;

    #pragma unroll 2
    for (int k0 = 0; k0 < K; k0 += 4) {
        float wv[4];
        #pragma unroll
        for (int j = 0; j < 4; j++)
            wv[j] = Wp[(k0 + j) * 128];

        #pragma unroll
        for (int j = 0; j < 4; j++) {
            const int k = k0 + j;
            const double2 x0 = *(const double2*)(In + k * TILE + r0);
            const double2 x1 = *(const double2*)(In + k * TILE + r0 + 4);
            const double2 x2 = *(const double2*)(In + k * TILE + r0 + 8);
            const double2 x3 = *(const double2*)(In + k * TILE + r0 + 12);
            const u64 w2 = dup2(wv[j]);
            acc[0] = ffma2(__double_as_longlong(x0.x), w2, acc[0]);
            acc[1] = ffma2(__double_as_longlong(x0.y), w2, acc[1]);
            acc[2] = ffma2(__double_as_longlong(x1.x), w2, acc[2]);
            acc[3] = ffma2(__double_as_longlong(x1.y), w2, acc[3]);
            acc[4] = ffma2(__double_as_longlong(x2.x), w2, acc[4]);
            acc[5] = ffma2(__double_as_longlong(x2.y), w2, acc[5]);
            acc[6] = ffma2(__double_as_longlong(x3.x), w2, acc[6]);
            acc[7] = ffma2(__double_as_longlong(x3.y), w2, acc[7]);
        }
    }

    const float bb = bias[c];
    float o[16];
    #pragma unroll
    for (int p = 0; p < 8; p++) {
        const float2 f = unpack2(acc[p]);
        o[2 * p]     = fmaxf(f.x + bb, 0.f);
        o[2 * p + 1] = fmaxf(f.y + bb, 0.f);
    }
    #pragma unroll
    for (int q = 0; q < 4; q++)
        *(float4*)(Out + c * TILE + r0 + 4 * q) =
            make_float4(o[4 * q], o[4 * q + 1], o[4 * q + 2], o[4 * q + 3]);
}

// ---------- LayerNorm(+affine,+ReLU) over feature dim on transposed buf A[256][32] ----------
__device__ __forceinline__ void ln_relu_T(float* A, const float* __restrict__ g,
                                          const float* __restrict__ b,
                                          float* red, float* mrow, float* rrow, int t)
{
    const int r = t & 31, kg = t >> 5;
    float s = 0.f, ss = 0.f;
    #pragma unroll 8
    for (int i = 0; i < 32; i++) {
        const float v = A[(kg * 32 + i) * TILE + r];
        s += v; ss += v * v;
    }
    red[kg * 32 + r] = s;
    red[256 + kg * 32 + r] = ss;
    __syncthreads();
    if (t < 32) {
        float S = 0.f, SS = 0.f;
        #pragma unroll
        for (int j = 0; j < 8; j++) { S += red[j * 32 + t]; SS += red[256 + j * 32 + t]; }
        const float m = S * (1.f / 256.f);
        const float var = SS * (1.f / 256.f) - m * m;
        mrow[t] = m;
        rrow[t] = rsqrtf(var + 1e-5f);
    }
    __syncthreads();
    const float m = mrow[r], rs = rrow[r];
    #pragma unroll 4
    for (int i = 0; i < 32; i++) {
        const int k = kg * 32 + i;
        const int idx = k * TILE + r;
        A[idx] = fmaxf((A[idx] - m) * rs * g[k] + b[k], 0.f);
    }
    __syncthreads();
}

__global__ void __launch_bounds__(NT, 3) moe_fused_kernel(
    const float* __restrict__ state,
    const float* __restrict__ rW1, const float* __restrict__ rb1,
    const float* __restrict__ rW2, const float* __restrict__ rb2,
    const float* __restrict__ eW1, const float* __restrict__ eb1,
    const float* __restrict__ eg1, const float* __restrict__ ebt1,
    const float* __restrict__ eW2, const float* __restrict__ eb2,
    const float* __restrict__ eg2, const float* __restrict__ ebt2,
    const float* __restrict__ eW3, const float* __restrict__ eb3,
    const float* __restrict__ vW1, const float* __restrict__ vb1,
    const float* __restrict__ vg,  const float* __restrict__ vbt,
    const float* __restrict__ vW2, const float* __restrict__ vb2,
    const float* __restrict__ vW3, const float* __restrict__ vb3,
    float* __restrict__ out)
{
    extern __shared__ float sm[];
    float* XsT   = sm;               // [44][32]
    float* A1    = sm + OFF_A1;      // [256][32]
    float* A2    = sm + OFF_A2;      // [256][32]
    float* red   = sm + OFF_RED;     // [512]
    float* mrow  = sm + OFF_MROW;    // [32]
    float* rrow  = sm + OFF_RROW;    // [32]
    float* lg    = sm + OFF_LG;      // [32][4]
    float* combT = sm + OFF_COMB;    // [4][32]

    const int t = threadIdx.x;
    const int row0 = blockIdx.x * TILE;

    // ---- load state tile transposed: XsT[k][r] ----
    for (int i = t; i < TILE * DD; i += NT) {
        const int r = i / DD, k = i - r * DD;
        XsT[k * TILE + r] = state[(size_t)row0 * DD + i];
    }
    __syncthreads();

    // ---- router hidden: relu(X @ rW1 + rb1) -> A2^T[128][32] ----
    gemm_to128_relu<DD>(XsT, rW1, rb1, A2, t);
    __syncthreads();

    // ---- router logits partials ----
    if (t < 128) {
        const int r = t & 31, kg = t >> 5;
        float a0 = 0.f, a1 = 0.f, a2 = 0.f, a3 = 0.f;
        #pragma unroll 4
        for (int i = 0; i < 32; i++) {
            const int k = kg * 32 + i;
            const float x = A2[k * TILE + r];
            a0 = fmaf(x, rW2[k * 4 + 0], a0);
            a1 = fmaf(x, rW2[k * 4 + 1], a1);
            a2 = fmaf(x, rW2[k * 4 + 2], a2);
            a3 = fmaf(x, rW2[k * 4 + 3], a3);
        }
        red[(0 * 4 + kg) * 32 + r] = a0;
        red[(1 * 4 + kg) * 32 + r] = a1;
        red[(2 * 4 + kg) * 32 + r] = a2;
        red[(3 * 4 + kg) * 32 + r] = a3;
    }
    __syncthreads();
    if (t < 128) {
        const int r = t & 31, e = t >> 5;
        float acc = rb2[e];
        #pragma unroll
        for (int kg = 0; kg < 4; kg++) acc += red[(e * 4 + kg) * 32 + r];
        lg[r * 4 + e] = acc;
    }
    __syncthreads();

    // ---- softmax, top-2, combine weights (transposed), router_probs out ----
    if (t < TILE) {
        float l[4];
        #pragma unroll
        for (int e = 0; e < 4; e++) l[e] = lg[t * 4 + e];
        const float m = fmaxf(fmaxf(l[0], l[1]), fmaxf(l[2], l[3]));
        float p[4], s = 0.f;
        #pragma unroll
        for (int e = 0; e < 4; e++) { p[e] = expf(l[e] - m); s += p[e]; }
        const float inv = 1.f / s;
        #pragma unroll
        for (int e = 0; e < 4; e++) p[e] *= inv;

        const size_t rbase = (size_t)NB * 17 + (size_t)(row0 + t) * 4;
        #pragma unroll
        for (int e = 0; e < 4; e++) out[rbase + e] = p[e];

        int i0 = 0; float v0 = p[0];
        #pragma unroll
        for (int e = 1; e < 4; e++) if (p[e] > v0) { v0 = p[e]; i0 = e; }
        int i1 = -1; float v1 = -1.f;
        #pragma unroll
        for (int e = 0; e < 4; e++) if (e != i0 && p[e] > v1) { v1 = p[e]; i1 = e; }
        const float denom = 1.f / (v0 + v1 + 1e-8f);
        #pragma unroll
        for (int e = 0; e < 4; e++) combT[e * 32 + t] = 0.f;
        combT[i0 * 32 + t] = v0 * denom;
        combT[i1 * 32 + t] = v1 * denom;
    }

    // ---- value net ----
    gemm_to256<DD>(XsT, vW1, vb1, A1, t);
    __syncthreads();
    ln_relu_T(A1, vg, vbt, red, mrow, rrow, t);       // includes trailing sync
    gemm_to128_relu<HH>(A1, vW2, vb2, A2, t);
    __syncthreads();
    {   // value = v2 @ vW3 + vb3
        const int r = t & 31, kg = t >> 5;
        float s = 0.f;
        #pragma unroll 4
        for (int i = 0; i < 16; i++) {
            const int k = kg * 16 + i;
            s = fmaf(A2[k * TILE + r], vW3[k], s);
        }
        red[kg * 32 + r] = s;
    }
    __syncthreads();
    if (t < 32) {
        float S = 0.f;
        #pragma unroll
        for (int j = 0; j < 8; j++) S += red[j * 32 + t];
        out[(size_t)NB * 16 + row0 + t] = S + vb3[0];
    }

    // ---- experts: dense over 4, weighted accumulate in packed registers ----
    const int ec = t & 15;    // output column 0..15
    const int ep = t >> 4;    // row pair 0..15 -> rows 2ep, 2ep+1
    u64 mix2 = 0ull;

    for (int e = 0; e < EE; e++) {
        const float* W1 = eW1 + (size_t)e * DD * HH;
        const float* W2 = eW2 + (size_t)e * HH * HH;
        const float* W3 = eW3 + (size_t)e * HH * 16;

        gemm_to256<DD>(XsT, W1, eb1 + e * HH, A1, t);
        __syncthreads();
        ln_relu_T(A1, eg1 + e * HH, ebt1 + e * HH, red, mrow, rrow, t);

        gemm_to256<HH>(A1, W2, eb2 + e * HH, A2, t);
        __syncthreads();
        ln_relu_T(A2, eg2 + e * HH, ebt2 + e * HH, red, mrow, rrow, t);

        // GEMM3: A2^T[256][32] @ W3[256][16], weighted by combine.
        // Weight LDGs batched 4-deep.
        u64 a2 = 0ull;
        const float* W3p = W3 + ec;
        #pragma unroll 2
        for (int k0 = 0; k0 < HH; k0 += 4) {
            float wv[4];
            #pragma unroll
            for (int j = 0; j < 4; j++) wv[j] = W3p[(k0 + j) * 16];
            #pragma unroll
            for (int j = 0; j < 4; j++) {
                const u64 x = __double_as_longlong(*(const double*)(A2 + (k0 + j) * TILE + 2 * ep));
                a2 = ffma2(x, dup2(wv[j]), a2);
            }
        }
        const u64 b2 = dup2(eb3[e * 16 + ec]);
        const u64 y  = fadd2(a2, b2);
        const u64 cw = __double_as_longlong(*(const double*)(combT + e * 32 + 2 * ep));
        mix2 = ffma2(cw, y, mix2);
        // no extra sync: next gemm writes A1 only; A2 rewrite is gated by later syncs
    }

    // ---- epilogue: alpha / beta ----
    {
        const float2 mm = unpack2(mix2);
        const float oA = softplus1(mm.x);
        const float oB = softplus1(mm.y);
        const size_t rowA = row0 + 2 * ep;
        const size_t rowB = rowA + 1;
        if (ec < AA) {
            out[rowA * AA + ec] = oA;
            out[rowB * AA + ec] = oB;
        } else {
            out[(size_t)NB * AA + rowA * AA + (ec - AA)] = oA;
            out[(size_t)NB * AA + rowB * AA + (ec - AA)] = oB;
        }
    }
}

extern "C" void kernel_launch(void* const* d_in, const int* in_sizes, int n_in,
                              void* d_out, int out_size) {
    const float* state = (const float*)d_in[0];
    const float* rW1   = (const float*)d_in[1];
    const float* rb1   = (const float*)d_in[2];
    const float* rW2   = (const float*)d_in[3];
    const float* rb2   = (const float*)d_in[4];
    const float* eW1   = (const float*)d_in[5];
    const float* eb1   = (const float*)d_in[6];
    const float* eg1   = (const float*)d_in[7];
    const float* ebt1  = (const float*)d_in[8];
    const float* eW2   = (const float*)d_in[9];
    const float* eb2   = (const float*)d_in[10];
    const float* eg2   = (const float*)d_in[11];
    const float* ebt2  = (const float*)d_in[12];
    const float* eW3   = (const float*)d_in[13];
    const float* eb3   = (const float*)d_in[14];
    const float* vW1   = (const float*)d_in[15];
    const float* vb1   = (const float*)d_in[16];
    const float* vg    = (const float*)d_in[17];
    const float* vbt   = (const float*)d_in[18];
    const float* vW2   = (const float*)d_in[19];
    const float* vb2   = (const float*)d_in[20];
    const float* vW3   = (const float*)d_in[21];
    const float* vb3   = (const float*)d_in[22];
    float* out = (float*)d_out;

    cudaFuncSetAttribute(moe_fused_kernel,
                         cudaFuncAttributeMaxDynamicSharedMemorySize, SMEM_BYTES);

    moe_fused_kernel<<<NB / TILE, NT, SMEM_BYTES>>>(
        state, rW1, rb1, rW2, rb2,
        eW1, eb1, eg1, ebt1, eW2, eb2, eg2, ebt2, eW3, eb3,
        vW1, vb1, vg, vbt, vW2, vb2, vW3, vb3, out);
}